// round 3
// baseline (speedup 1.0000x reference)
#include <cuda_runtime.h>
#include <cuda_bf16.h>
#include <math.h>

// Problem constants
#define BB 2
#define SS 2048
#define DD 1024
#define HH 16
#define HD 64
#define CC 1024
#define MM (BB*SS)          // 4096 rows
#define D3 (3*DD)           // 3072
#define D4 (4*DD)           // 4096
#define D6 (6*DD)           // 6144

// Scratch (device globals; no allocation allowed)
__device__ float g_mods[BB*D6];
__device__ float g_h[MM*DD];       // LN1 out, later LN2 out
__device__ float g_qkv[MM*D3];
__device__ float g_o[MM*DD];
__device__ float g_xmid[MM*DD];
__device__ float g_mlp[MM*D4];

// ---------------------------------------------------------------------------
// 1) mods = c @ ada_w.T + ada_b   -> g_mods[b][j], j in [0,6144)
//    one warp per output element
// ---------------------------------------------------------------------------
__global__ void k_mods(const float* __restrict__ c,
                       const float* __restrict__ ada_w,
                       const float* __restrict__ ada_b)
{
    int gw = (blockIdx.x * blockDim.x + threadIdx.x) >> 5;
    int lane = threadIdx.x & 31;
    if (gw >= BB * D6) return;
    int b = gw / D6, j = gw - b * D6;
    const float* cv = c + (size_t)b * CC;
    const float* wv = ada_w + (size_t)j * CC;
    float s = 0.f;
    #pragma unroll 4
    for (int k = lane; k < CC; k += 32) s += cv[k] * wv[k];
    #pragma unroll
    for (int o = 16; o > 0; o >>= 1) s += __shfl_xor_sync(0xffffffffu, s, o);
    if (lane == 0) g_mods[gw] = s + ada_b[j];
}

// ---------------------------------------------------------------------------
// 2) LayerNorm + adaLN modulate: out = LN(x)*w * (1+scale) + shift
//    one block (256 thr) per row of 1024
// ---------------------------------------------------------------------------
__global__ void __launch_bounds__(256) k_ln_mod(const float* __restrict__ x,
                                                const float* __restrict__ w,
                                                int scale_off, int shift_off,
                                                float* __restrict__ out)
{
    int row = blockIdx.x;          // 0..4095
    int b = row >> 11;             // row / 2048
    const float4* xr = (const float4*)(x + (size_t)row * DD);
    int t = threadIdx.x;
    float4 xv = xr[t];
    float s  = xv.x + xv.y + xv.z + xv.w;
    float ss = xv.x*xv.x + xv.y*xv.y + xv.z*xv.z + xv.w*xv.w;
    #pragma unroll
    for (int o = 16; o > 0; o >>= 1) {
        s  += __shfl_xor_sync(0xffffffffu, s, o);
        ss += __shfl_xor_sync(0xffffffffu, ss, o);
    }
    __shared__ float sm[8], sm2[8];
    int wid = t >> 5, lane = t & 31;
    if (lane == 0) { sm[wid] = s; sm2[wid] = ss; }
    __syncthreads();
    if (t == 0) {
        float a = 0.f, a2 = 0.f;
        #pragma unroll
        for (int i = 0; i < 8; i++) { a += sm[i]; a2 += sm2[i]; }
        sm[0] = a; sm2[0] = a2;
    }
    __syncthreads();
    float mu  = sm[0]  * (1.f / DD);
    float var = sm2[0] * (1.f / DD) - mu * mu;
    float rstd = rsqrtf(var + 1e-5f);
    const float* md = g_mods + (size_t)b * D6;
    int j = t * 4;
    float4 wv = *(const float4*)(w + j);
    float4 sc = *(const float4*)(md + scale_off + j);
    float4 sh = *(const float4*)(md + shift_off + j);
    float4 ov;
    ov.x = (xv.x - mu) * rstd * wv.x * (1.f + sc.x) + sh.x;
    ov.y = (xv.y - mu) * rstd * wv.y * (1.f + sc.y) + sh.y;
    ov.z = (xv.z - mu) * rstd * wv.z * (1.f + sc.z) + sh.z;
    ov.w = (xv.w - mu) * rstd * wv.w * (1.f + sc.w) + sh.w;
    ((float4*)(out + (size_t)row * DD))[t] = ov;
}

// ---------------------------------------------------------------------------
// 3) Tiled fp32 GEMM: C[M,N] = A[M,K] @ Bw[N,K]^T  (+ epilogues)
//    BM=BN=64, BK=32, 256 threads, 4x4 per thread (strided mapping)
//    EPI: 0=store, 1=gate*acc+add, 2=gelu(acc+bias), 3=gate*(acc+bias)+add
// ---------------------------------------------------------------------------
template<int EPI>
__global__ void __launch_bounds__(256) k_gemm(const float* __restrict__ A,
                                              const float* __restrict__ Bw,
                                              const float* __restrict__ bias,
                                              const float* __restrict__ add,
                                              float* __restrict__ C,
                                              int M, int N, int K, int gate_off)
{
    __shared__ float As[64][33];
    __shared__ float Bs[64][33];
    const int tid = threadIdx.x;
    const int tx = tid & 15, ty = tid >> 4;
    const int bm = blockIdx.y * 64, bn = blockIdx.x * 64;
    const float* Ap = A  + (size_t)bm * K;
    const float* Bp = Bw + (size_t)bn * K;
    float acc[4][4] = {};

    for (int k0 = 0; k0 < K; k0 += 32) {
        #pragma unroll
        for (int l = 0; l < 2; l++) {
            int id = tid + l * 256;
            int r = id >> 3, c4 = (id & 7) * 4;
            float4 av = *(const float4*)(Ap + (size_t)r * K + k0 + c4);
            As[r][c4] = av.x; As[r][c4+1] = av.y; As[r][c4+2] = av.z; As[r][c4+3] = av.w;
            float4 bv = *(const float4*)(Bp + (size_t)r * K + k0 + c4);
            Bs[r][c4] = bv.x; Bs[r][c4+1] = bv.y; Bs[r][c4+2] = bv.z; Bs[r][c4+3] = bv.w;
        }
        __syncthreads();
        #pragma unroll
        for (int kk = 0; kk < 32; kk++) {
            float a0 = As[ty     ][kk], a1 = As[ty + 16][kk],
                  a2 = As[ty + 32][kk], a3 = As[ty + 48][kk];
            float b0 = Bs[tx     ][kk], b1 = Bs[tx + 16][kk],
                  b2 = Bs[tx + 32][kk], b3 = Bs[tx + 48][kk];
            acc[0][0] += a0*b0; acc[0][1] += a0*b1; acc[0][2] += a0*b2; acc[0][3] += a0*b3;
            acc[1][0] += a1*b0; acc[1][1] += a1*b1; acc[1][2] += a1*b2; acc[1][3] += a1*b3;
            acc[2][0] += a2*b0; acc[2][1] += a2*b1; acc[2][2] += a2*b2; acc[2][3] += a2*b3;
            acc[3][0] += a3*b0; acc[3][1] += a3*b1; acc[3][2] += a3*b2; acc[3][3] += a3*b3;
        }
        __syncthreads();
    }

    #pragma unroll
    for (int i = 0; i < 4; i++) {
        int m = bm + ty + i * 16;
        int bb = m >> 11;
        #pragma unroll
        for (int j = 0; j < 4; j++) {
            int n = bn + tx + j * 16;
            float v = acc[i][j];
            size_t off = (size_t)m * N + n;
            if (EPI == 0) {
                C[off] = v;
            } else if (EPI == 1) {
                C[off] = g_mods[(size_t)bb * D6 + gate_off + n] * v + add[off];
            } else if (EPI == 2) {
                float tt = v + bias[n];
                C[off] = 0.5f * tt * (1.f + erff(tt * 0.70710678118654752f));
            } else {
                float tt = v + bias[n];
                C[off] = g_mods[(size_t)bb * D6 + gate_off + n] * tt
                         + add[(size_t)m * DD + n];
            }
        }
    }
}

// ---------------------------------------------------------------------------
// 4) RoPE applied in-place to all of q,k,v (reference applies it to v too)
// ---------------------------------------------------------------------------
__global__ void k_rope(const float* __restrict__ cosT, const float* __restrict__ sinT)
{
    int t = blockIdx.x * blockDim.x + threadIdx.x;
    // pairs: b * s * 3 * H * 32
    if (t >= BB * SS * 3 * HH * 32) return;
    int d  = t & 31;  int u = t >> 5;
    int h  = u & 15;  u >>= 4;
    int m3 = u % 3;   u /= 3;
    int s  = u & 2047;
    int b  = u >> 11;
    size_t base = ((((size_t)(b * SS + s)) * 3 + m3) * HH + h) * HD;
    float c  = cosT[s * HD + d];
    float sn = sinT[s * HD + d];
    float v1 = g_qkv[base + d];
    float v2 = g_qkv[base + d + 32];
    g_qkv[base + d]      = v1 * c - v2 * sn;
    g_qkv[base + d + 32] = v2 * c + v1 * sn;   // cos/sin repeat at d+32
}

// ---------------------------------------------------------------------------
// 5) Flash attention, fp32. Br=64, Bc=32, 128 threads.
//    Each thread: 2 query rows (rg) x 8 key cols (cg) for scores;
//    2 rows x 16 output dims (cg) for PV.
// ---------------------------------------------------------------------------
__global__ void __launch_bounds__(128) k_attn()
{
    __shared__ float Qs[64][65];
    __shared__ float Ks[32][65];
    __shared__ float Vs[32][65];
    __shared__ float Ps[64][33];

    int qt = blockIdx.x, h = blockIdx.y, b = blockIdx.z;
    int tid = threadIdx.x;
    int rg = tid >> 2, cg = tid & 3;
    int r0 = rg * 2, r1 = r0 + 1;

    // Load Q tile 64x64
    size_t qbase = (((size_t)(b * SS + qt * 64)) * 3 + 0) * DD + h * HD;
    #pragma unroll
    for (int l = 0; l < 8; l++) {
        int id = tid + l * 128;
        int r = id >> 4, c4 = (id & 15) * 4;
        float4 v = *(const float4*)(g_qkv + qbase + (size_t)r * D3 + c4);
        Qs[r][c4] = v.x; Qs[r][c4+1] = v.y; Qs[r][c4+2] = v.z; Qs[r][c4+3] = v.w;
    }

    float m0 = -1e30f, m1 = -1e30f, l0 = 0.f, l1 = 0.f;
    float oa0[16], oa1[16];
    #pragma unroll
    for (int c = 0; c < 16; c++) { oa0[c] = 0.f; oa1[c] = 0.f; }

    for (int kt = 0; kt < SS / 32; kt++) {
        __syncthreads();   // protect Ks/Vs from previous iteration readers
        size_t kbase = (((size_t)(b * SS + kt * 32)) * 3 + 1) * DD + h * HD;
        size_t vbase = kbase + DD;
        #pragma unroll
        for (int l = 0; l < 4; l++) {
            int id = tid + l * 128;
            int r = id >> 4, c4 = (id & 15) * 4;
            float4 kv = *(const float4*)(g_qkv + kbase + (size_t)r * D3 + c4);
            Ks[r][c4] = kv.x; Ks[r][c4+1] = kv.y; Ks[r][c4+2] = kv.z; Ks[r][c4+3] = kv.w;
            float4 vv = *(const float4*)(g_qkv + vbase + (size_t)r * D3 + c4);
            Vs[r][c4] = vv.x; Vs[r][c4+1] = vv.y; Vs[r][c4+2] = vv.z; Vs[r][c4+3] = vv.w;
        }
        __syncthreads();

        // scores: 2 rows x 8 cols
        float s0[8], s1[8];
        #pragma unroll
        for (int c = 0; c < 8; c++) { s0[c] = 0.f; s1[c] = 0.f; }
        #pragma unroll 8
        for (int d = 0; d < 64; d++) {
            float qa = Qs[r0][d], qb = Qs[r1][d];
            #pragma unroll
            for (int c = 0; c < 8; c++) {
                float kk = Ks[cg * 8 + c][d];
                s0[c] += qa * kk;
                s1[c] += qb * kk;
            }
        }
        float mt0 = -1e30f, mt1 = -1e30f;
        #pragma unroll
        for (int c = 0; c < 8; c++) {
            s0[c] *= 0.125f; s1[c] *= 0.125f;
            mt0 = fmaxf(mt0, s0[c]); mt1 = fmaxf(mt1, s1[c]);
        }
        // reduce max across the 4 cg lanes (consecutive lanes in warp)
        mt0 = fmaxf(mt0, __shfl_xor_sync(0xffffffffu, mt0, 1));
        mt0 = fmaxf(mt0, __shfl_xor_sync(0xffffffffu, mt0, 2));
        mt1 = fmaxf(mt1, __shfl_xor_sync(0xffffffffu, mt1, 1));
        mt1 = fmaxf(mt1, __shfl_xor_sync(0xffffffffu, mt1, 2));
        float mn0 = fmaxf(m0, mt0), mn1 = fmaxf(m1, mt1);
        float a0 = __expf(m0 - mn0), a1 = __expf(m1 - mn1);
        float lt0 = 0.f, lt1 = 0.f;
        #pragma unroll
        for (int c = 0; c < 8; c++) {
            float p0 = __expf(s0[c] - mn0);
            float p1 = __expf(s1[c] - mn1);
            Ps[r0][cg * 8 + c] = p0;
            Ps[r1][cg * 8 + c] = p1;
            lt0 += p0; lt1 += p1;
        }
        lt0 += __shfl_xor_sync(0xffffffffu, lt0, 1);
        lt0 += __shfl_xor_sync(0xffffffffu, lt0, 2);
        lt1 += __shfl_xor_sync(0xffffffffu, lt1, 1);
        lt1 += __shfl_xor_sync(0xffffffffu, lt1, 2);
        l0 = l0 * a0 + lt0;  m0 = mn0;
        l1 = l1 * a1 + lt1;  m1 = mn1;
        #pragma unroll
        for (int c = 0; c < 16; c++) { oa0[c] *= a0; oa1[c] *= a1; }
        __syncwarp();   // Ps rows of this rowgroup written by same-warp lanes

        // PV: accumulate over 32 cols for our 16 output dims
        #pragma unroll 4
        for (int col = 0; col < 32; col++) {
            float p0 = Ps[r0][col], p1 = Ps[r1][col];
            #pragma unroll
            for (int c = 0; c < 16; c++) {
                float vv = Vs[col][cg * 16 + c];
                oa0[c] += p0 * vv;
                oa1[c] += p1 * vv;
            }
        }
    }

    float i0 = 1.f / l0, i1 = 1.f / l1;
    size_t ob0 = ((size_t)(b * SS + qt * 64 + r0)) * DD + h * HD + cg * 16;
    size_t ob1 = ob0 + DD;  // next sequence row
    #pragma unroll
    for (int c = 0; c < 16; c++) {
        g_o[ob0 + c] = oa0[c] * i0;
        g_o[ob1 + c] = oa1[c] * i1;
    }
}

// ---------------------------------------------------------------------------
extern "C" void kernel_launch(void* const* d_in, const int* in_sizes, int n_in,
                              void* d_out, int out_size)
{
    const float* x          = (const float*)d_in[0];
    const float* rotary_cos = (const float*)d_in[1];
    const float* rotary_sin = (const float*)d_in[2];
    const float* c          = (const float*)d_in[3];
    const float* norm1_w    = (const float*)d_in[4];
    const float* qkv_w      = (const float*)d_in[5];
    const float* out_w      = (const float*)d_in[6];
    const float* norm2_w    = (const float*)d_in[7];
    const float* fc1_w      = (const float*)d_in[8];
    const float* fc1_b      = (const float*)d_in[9];
    const float* fc2_w      = (const float*)d_in[10];
    const float* fc2_b      = (const float*)d_in[11];
    const float* ada_w      = (const float*)d_in[12];
    const float* ada_b      = (const float*)d_in[13];
    float* out = (float*)d_out;

    float* p_h;    cudaGetSymbolAddress((void**)&p_h, g_h);
    float* p_qkv;  cudaGetSymbolAddress((void**)&p_qkv, g_qkv);
    float* p_o;    cudaGetSymbolAddress((void**)&p_o, g_o);
    float* p_xmid; cudaGetSymbolAddress((void**)&p_xmid, g_xmid);
    float* p_mlp;  cudaGetSymbolAddress((void**)&p_mlp, g_mlp);

    // 1) adaLN mods
    k_mods<<<(BB * D6 * 32 + 255) / 256, 256>>>(c, ada_w, ada_b);

    // 2) LN1 + modulate (scale_msa @1024, shift_msa @0) -> g_h
    k_ln_mod<<<MM, 256>>>(x, norm1_w, 1 * DD, 0 * DD, p_h);

    // 3) QKV GEMM: [4096,1024] @ [3072,1024]^T -> g_qkv
    k_gemm<0><<<dim3(D3 / 64, MM / 64), 256>>>(p_h, qkv_w, nullptr, nullptr,
                                               p_qkv, MM, D3, DD, 0);

    // 4) RoPE in place on q,k,v
    k_rope<<<(BB * SS * 3 * HH * 32) / 256, 256>>>(rotary_cos, rotary_sin);

    // 5) Attention -> g_o
    k_attn<<<dim3(SS / 64, HH, BB), 128>>>();

    // 6) out proj + gate_msa (@2048) + residual(x) -> g_xmid
    k_gemm<1><<<dim3(DD / 64, MM / 64), 256>>>(p_o, out_w, nullptr, x,
                                               p_xmid, MM, DD, DD, 2 * DD);

    // 7) LN2 + modulate (scale_mlp @4096, shift_mlp @3072) -> g_h
    k_ln_mod<<<MM, 256>>>(p_xmid, norm2_w, 4 * DD, 3 * DD, p_h);

    // 8) fc1 + bias + exact GELU -> g_mlp
    k_gemm<2><<<dim3(D4 / 64, MM / 64), 256>>>(p_h, fc1_w, fc1_b, nullptr,
                                               p_mlp, MM, D4, DD, 0);

    // 9) fc2 + bias, gate_mlp (@5120), + residual(g_xmid) -> d_out
    k_gemm<3><<<dim3(DD / 64, MM / 64), 256>>>(p_mlp, fc2_w, fc2_b, p_xmid,
                                               out, MM, DD, D4, 5 * DD);
}

// round 4
// speedup vs baseline: 1.1626x; 1.1626x over previous
#include <cuda_runtime.h>
#include <cuda_bf16.h>
#include <math.h>

// Problem constants
#define BB 2
#define SS 2048
#define DD 1024
#define HH 16
#define HD 64
#define CC 1024
#define MM (BB*SS)          // 4096 rows
#define D3 (3*DD)           // 3072
#define D4 (4*DD)           // 4096
#define D6 (6*DD)           // 6144

typedef unsigned long long u64;

__device__ __forceinline__ u64 dup2(float v) {
    u64 r; asm("mov.b64 %0,{%1,%1};" : "=l"(r) : "f"(v)); return r;
}
__device__ __forceinline__ u64 ffma2(u64 a, u64 b, u64 c) {
    u64 d; asm("fma.rn.f32x2 %0,%1,%2,%3;" : "=l"(d) : "l"(a), "l"(b), "l"(c)); return d;
}
__device__ __forceinline__ u64 fmul2(u64 a, u64 b) {
    u64 d; asm("mul.rn.f32x2 %0,%1,%2;" : "=l"(d) : "l"(a), "l"(b)); return d;
}
__device__ __forceinline__ float2 unpk(u64 v) {
    float2 r; asm("mov.b64 {%0,%1},%2;" : "=f"(r.x), "=f"(r.y) : "l"(v)); return r;
}

// Scratch (device globals; no allocation allowed)
__device__ float g_mods[BB*D6];
__device__ float g_h[MM*DD];       // LN1 out, later LN2 out
__device__ float g_qkv[MM*D3];
__device__ float g_o[MM*DD];
__device__ float g_xmid[MM*DD];
__device__ float g_mlp[MM*D4];

// ---------------------------------------------------------------------------
// 1) mods = c @ ada_w.T + ada_b
// ---------------------------------------------------------------------------
__global__ void k_mods(const float* __restrict__ c,
                       const float* __restrict__ ada_w,
                       const float* __restrict__ ada_b)
{
    int gw = (blockIdx.x * blockDim.x + threadIdx.x) >> 5;
    int lane = threadIdx.x & 31;
    if (gw >= BB * D6) return;
    int b = gw / D6, j = gw - b * D6;
    const float* cv = c + (size_t)b * CC;
    const float* wv = ada_w + (size_t)j * CC;
    float s = 0.f;
    #pragma unroll 4
    for (int k = lane; k < CC; k += 32) s += cv[k] * wv[k];
    #pragma unroll
    for (int o = 16; o > 0; o >>= 1) s += __shfl_xor_sync(0xffffffffu, s, o);
    if (lane == 0) g_mods[gw] = s + ada_b[j];
}

// ---------------------------------------------------------------------------
// 2) LayerNorm + adaLN modulate
// ---------------------------------------------------------------------------
__global__ void __launch_bounds__(256) k_ln_mod(const float* __restrict__ x,
                                                const float* __restrict__ w,
                                                int scale_off, int shift_off,
                                                float* __restrict__ out)
{
    int row = blockIdx.x;
    int b = row >> 11;
    const float4* xr = (const float4*)(x + (size_t)row * DD);
    int t = threadIdx.x;
    float4 xv = xr[t];
    float s  = xv.x + xv.y + xv.z + xv.w;
    float ss = xv.x*xv.x + xv.y*xv.y + xv.z*xv.z + xv.w*xv.w;
    #pragma unroll
    for (int o = 16; o > 0; o >>= 1) {
        s  += __shfl_xor_sync(0xffffffffu, s, o);
        ss += __shfl_xor_sync(0xffffffffu, ss, o);
    }
    __shared__ float sm[8], sm2[8];
    int wid = t >> 5, lane = t & 31;
    if (lane == 0) { sm[wid] = s; sm2[wid] = ss; }
    __syncthreads();
    if (t == 0) {
        float a = 0.f, a2 = 0.f;
        #pragma unroll
        for (int i = 0; i < 8; i++) { a += sm[i]; a2 += sm2[i]; }
        sm[0] = a; sm2[0] = a2;
    }
    __syncthreads();
    float mu  = sm[0]  * (1.f / DD);
    float var = sm2[0] * (1.f / DD) - mu * mu;
    float rstd = rsqrtf(var + 1e-5f);
    const float* md = g_mods + (size_t)b * D6;
    int j = t * 4;
    float4 wv = *(const float4*)(w + j);
    float4 sc = *(const float4*)(md + scale_off + j);
    float4 sh = *(const float4*)(md + shift_off + j);
    float4 ov;
    ov.x = (xv.x - mu) * rstd * wv.x * (1.f + sc.x) + sh.x;
    ov.y = (xv.y - mu) * rstd * wv.y * (1.f + sc.y) + sh.y;
    ov.z = (xv.z - mu) * rstd * wv.z * (1.f + sc.z) + sh.z;
    ov.w = (xv.w - mu) * rstd * wv.w * (1.f + sc.w) + sh.w;
    ((float4*)(out + (size_t)row * DD))[t] = ov;
}

// ---------------------------------------------------------------------------
// 3) Tiled fp32 GEMM with packed f32x2 FMA.
//    C[M,N] = A[M,K] @ Bw[N,K]^T (+ epilogue)
//    128x128 block, BK=16, 256 threads, 8x8 per thread.
//    SMEM k-major: As[k][m], Bs[k][n]; B fragment read as packed pairs.
//    EPI: 0=store, 1=gate*acc+add, 2=gelu(acc+bias), 3=gate*(acc+bias)+add
// ---------------------------------------------------------------------------
template<int EPI>
__global__ void __launch_bounds__(256) k_gemm(const float* __restrict__ A,
                                              const float* __restrict__ Bw,
                                              const float* __restrict__ bias,
                                              const float* __restrict__ add,
                                              float* __restrict__ C,
                                              int M, int N, int K, int gate_off)
{
    __shared__ float As[16][132];
    __shared__ float Bs[16][132];
    const int tid = threadIdx.x;
    const int tx = tid & 15, ty = tid >> 4;
    const int bm = blockIdx.y * 128, bn = blockIdx.x * 128;
    const int lm = tid >> 1;          // row within tile, 0..127
    const int lk = (tid & 1) * 8;     // k offset, 0 or 8
    const float* Ap = A  + (size_t)(bm + lm) * K + lk;
    const float* Bp = Bw + (size_t)(bn + lm) * K + lk;

    u64 acc[8][4];
    #pragma unroll
    for (int i = 0; i < 8; i++)
        #pragma unroll
        for (int j = 0; j < 4; j++) acc[i][j] = 0ull;

    for (int k0 = 0; k0 < K; k0 += 16) {
        float4 a0 = *(const float4*)(Ap + k0);
        float4 a1 = *(const float4*)(Ap + k0 + 4);
        float4 b0 = *(const float4*)(Bp + k0);
        float4 b1 = *(const float4*)(Bp + k0 + 4);
        __syncthreads();
        As[lk+0][lm] = a0.x; As[lk+1][lm] = a0.y; As[lk+2][lm] = a0.z; As[lk+3][lm] = a0.w;
        As[lk+4][lm] = a1.x; As[lk+5][lm] = a1.y; As[lk+6][lm] = a1.z; As[lk+7][lm] = a1.w;
        Bs[lk+0][lm] = b0.x; Bs[lk+1][lm] = b0.y; Bs[lk+2][lm] = b0.z; Bs[lk+3][lm] = b0.w;
        Bs[lk+4][lm] = b1.x; Bs[lk+5][lm] = b1.y; Bs[lk+6][lm] = b1.z; Bs[lk+7][lm] = b1.w;
        __syncthreads();
        #pragma unroll
        for (int kk = 0; kk < 16; kk++) {
            float4 av0 = *(const float4*)&As[kk][ty * 8];
            float4 av1 = *(const float4*)&As[kk][ty * 8 + 4];
            ulonglong2 bv0 = *(const ulonglong2*)&Bs[kk][tx * 8];
            ulonglong2 bv1 = *(const ulonglong2*)&Bs[kk][tx * 8 + 4];
            u64 bq[4] = { bv0.x, bv0.y, bv1.x, bv1.y };
            float aa[8] = { av0.x, av0.y, av0.z, av0.w,
                            av1.x, av1.y, av1.z, av1.w };
            #pragma unroll
            for (int i = 0; i < 8; i++) {
                u64 ad = dup2(aa[i]);
                #pragma unroll
                for (int j = 0; j < 4; j++)
                    acc[i][j] = ffma2(ad, bq[j], acc[i][j]);
            }
        }
    }

    #pragma unroll
    for (int i = 0; i < 8; i++) {
        int m = bm + ty * 8 + i;
        int bb = m >> 11;
        int n0 = bn + tx * 8;
        float ov[8];
        #pragma unroll
        for (int j = 0; j < 4; j++) {
            float2 u = unpk(acc[i][j]);
            ov[2*j] = u.x; ov[2*j+1] = u.y;
        }
        #pragma unroll
        for (int j = 0; j < 8; j++) {
            int n = n0 + j;
            float v = ov[j];
            if (EPI == 0) {
                // passthrough
            } else if (EPI == 1) {
                v = g_mods[(size_t)bb * D6 + gate_off + n] * v
                    + add[(size_t)m * N + n];
            } else if (EPI == 2) {
                float tt = v + bias[n];
                v = 0.5f * tt * (1.f + erff(tt * 0.70710678118654752f));
            } else {
                float tt = v + bias[n];
                v = g_mods[(size_t)bb * D6 + gate_off + n] * tt
                    + add[(size_t)m * DD + n];
            }
            ov[j] = v;
        }
        float4 w0 = make_float4(ov[0], ov[1], ov[2], ov[3]);
        float4 w1 = make_float4(ov[4], ov[5], ov[6], ov[7]);
        *(float4*)&C[(size_t)m * N + n0]     = w0;
        *(float4*)&C[(size_t)m * N + n0 + 4] = w1;
    }
}

// ---------------------------------------------------------------------------
// 4) RoPE in place on all of q,k,v (reference applies it to v too)
// ---------------------------------------------------------------------------
__global__ void k_rope(const float* __restrict__ cosT, const float* __restrict__ sinT)
{
    int t = blockIdx.x * blockDim.x + threadIdx.x;
    if (t >= BB * SS * 3 * HH * 32) return;
    int d  = t & 31;  int u = t >> 5;
    int h  = u & 15;  u >>= 4;
    int m3 = u % 3;   u /= 3;
    int s  = u & 2047;
    int b  = u >> 11;
    size_t base = ((((size_t)(b * SS + s)) * 3 + m3) * HH + h) * HD;
    float c  = cosT[s * HD + d];
    float sn = sinT[s * HD + d];
    float v1 = g_qkv[base + d];
    float v2 = g_qkv[base + d + 32];
    g_qkv[base + d]      = v1 * c - v2 * sn;
    g_qkv[base + d + 32] = v2 * c + v1 * sn;
}

// ---------------------------------------------------------------------------
// 5) Flash attention fp32 with packed f32x2 math. Br=64, Bc=32, 128 threads.
//    Thread: 2 rows x 8 score cols (packed as 4 f32x2),
//            2 rows x 16 out dims (packed as 8 f32x2).
//    K stored transposed in SMEM so score cols pack contiguously.
// ---------------------------------------------------------------------------
__global__ void __launch_bounds__(128) k_attn()
{
    __shared__ float Qs[64][68];
    __shared__ float Kts[64][36];   // [d][token]
    __shared__ float Vs[32][68];
    __shared__ float Ps[64][33];

    int qt = blockIdx.x, h = blockIdx.y, b = blockIdx.z;
    int tid = threadIdx.x;
    int rg = tid >> 2, cg = tid & 3;
    int r0 = rg * 2, r1 = r0 + 1;

    // Load Q tile 64x64
    size_t qbase = (((size_t)(b * SS + qt * 64)) * 3 + 0) * DD + h * HD;
    #pragma unroll
    for (int l = 0; l < 8; l++) {
        int id = tid + l * 128;
        int r = id >> 4, c4 = (id & 15) * 4;
        float4 v = *(const float4*)(g_qkv + qbase + (size_t)r * D3 + c4);
        *(float4*)&Qs[r][c4] = v;
    }

    float m0 = -1e30f, m1 = -1e30f, l0 = 0.f, l1 = 0.f;
    u64 oa0[8], oa1[8];
    #pragma unroll
    for (int c = 0; c < 8; c++) { oa0[c] = 0ull; oa1[c] = 0ull; }

    for (int kt = 0; kt < SS / 32; kt++) {
        __syncthreads();   // previous iteration readers done with Ks/Vs
        size_t kbase = (((size_t)(b * SS + kt * 32)) * 3 + 1) * DD + h * HD;
        size_t vbase = kbase + DD;
        #pragma unroll
        for (int l = 0; l < 4; l++) {
            int id = tid + l * 128;
            int r = id >> 4, c4 = (id & 15) * 4;   // r: token, c4: dim
            float4 kv = *(const float4*)(g_qkv + kbase + (size_t)r * D3 + c4);
            Kts[c4+0][r] = kv.x; Kts[c4+1][r] = kv.y;
            Kts[c4+2][r] = kv.z; Kts[c4+3][r] = kv.w;
            float4 vv = *(const float4*)(g_qkv + vbase + (size_t)r * D3 + c4);
            *(float4*)&Vs[r][c4] = vv;
        }
        __syncthreads();

        // scores: 2 rows x 8 cols, packed along cols
        u64 s20[4] = {0ull,0ull,0ull,0ull};
        u64 s21[4] = {0ull,0ull,0ull,0ull};
        #pragma unroll 4
        for (int d4 = 0; d4 < 64; d4 += 4) {
            float4 q0 = *(const float4*)&Qs[r0][d4];
            float4 q1 = *(const float4*)&Qs[r1][d4];
            float qa[4] = { q0.x, q0.y, q0.z, q0.w };
            float qb[4] = { q1.x, q1.y, q1.z, q1.w };
            #pragma unroll
            for (int dd = 0; dd < 4; dd++) {
                ulonglong2 k0v = *(const ulonglong2*)&Kts[d4+dd][cg * 8];
                ulonglong2 k1v = *(const ulonglong2*)&Kts[d4+dd][cg * 8 + 4];
                u64 qd0 = dup2(qa[dd]);
                u64 qd1 = dup2(qb[dd]);
                s20[0] = ffma2(qd0, k0v.x, s20[0]);
                s20[1] = ffma2(qd0, k0v.y, s20[1]);
                s20[2] = ffma2(qd0, k1v.x, s20[2]);
                s20[3] = ffma2(qd0, k1v.y, s20[3]);
                s21[0] = ffma2(qd1, k0v.x, s21[0]);
                s21[1] = ffma2(qd1, k0v.y, s21[1]);
                s21[2] = ffma2(qd1, k1v.x, s21[2]);
                s21[3] = ffma2(qd1, k1v.y, s21[3]);
            }
        }
        float s0[8], s1[8];
        #pragma unroll
        for (int j = 0; j < 4; j++) {
            float2 u0 = unpk(s20[j]); s0[2*j] = u0.x; s0[2*j+1] = u0.y;
            float2 u1 = unpk(s21[j]); s1[2*j] = u1.x; s1[2*j+1] = u1.y;
        }

        float mt0 = -1e30f, mt1 = -1e30f;
        #pragma unroll
        for (int c = 0; c < 8; c++) {
            s0[c] *= 0.125f; s1[c] *= 0.125f;
            mt0 = fmaxf(mt0, s0[c]); mt1 = fmaxf(mt1, s1[c]);
        }
        mt0 = fmaxf(mt0, __shfl_xor_sync(0xffffffffu, mt0, 1));
        mt0 = fmaxf(mt0, __shfl_xor_sync(0xffffffffu, mt0, 2));
        mt1 = fmaxf(mt1, __shfl_xor_sync(0xffffffffu, mt1, 1));
        mt1 = fmaxf(mt1, __shfl_xor_sync(0xffffffffu, mt1, 2));
        float mn0 = fmaxf(m0, mt0), mn1 = fmaxf(m1, mt1);
        float a0 = __expf(m0 - mn0), a1 = __expf(m1 - mn1);
        float lt0 = 0.f, lt1 = 0.f;
        #pragma unroll
        for (int c = 0; c < 8; c++) {
            float p0 = __expf(s0[c] - mn0);
            float p1 = __expf(s1[c] - mn1);
            Ps[r0][cg * 8 + c] = p0;
            Ps[r1][cg * 8 + c] = p1;
            lt0 += p0; lt1 += p1;
        }
        lt0 += __shfl_xor_sync(0xffffffffu, lt0, 1);
        lt0 += __shfl_xor_sync(0xffffffffu, lt0, 2);
        lt1 += __shfl_xor_sync(0xffffffffu, lt1, 1);
        lt1 += __shfl_xor_sync(0xffffffffu, lt1, 2);
        l0 = l0 * a0 + lt0;  m0 = mn0;
        l1 = l1 * a1 + lt1;  m1 = mn1;
        u64 a0d = dup2(a0), a1d = dup2(a1);
        #pragma unroll
        for (int c = 0; c < 8; c++) {
            oa0[c] = fmul2(oa0[c], a0d);
            oa1[c] = fmul2(oa1[c], a1d);
        }
        __syncwarp();   // Ps rows of this rowgroup written by same-warp lanes

        // PV: 32 cols into 16 out dims (8 packed pairs) per row
        #pragma unroll 4
        for (int col = 0; col < 32; col++) {
            float p0 = Ps[r0][col], p1 = Ps[r1][col];
            ulonglong2 v0 = *(const ulonglong2*)&Vs[col][cg * 16];
            ulonglong2 v1 = *(const ulonglong2*)&Vs[col][cg * 16 + 4];
            ulonglong2 v2 = *(const ulonglong2*)&Vs[col][cg * 16 + 8];
            ulonglong2 v3 = *(const ulonglong2*)&Vs[col][cg * 16 + 12];
            u64 pd0 = dup2(p0), pd1 = dup2(p1);
            oa0[0] = ffma2(pd0, v0.x, oa0[0]);
            oa0[1] = ffma2(pd0, v0.y, oa0[1]);
            oa0[2] = ffma2(pd0, v1.x, oa0[2]);
            oa0[3] = ffma2(pd0, v1.y, oa0[3]);
            oa0[4] = ffma2(pd0, v2.x, oa0[4]);
            oa0[5] = ffma2(pd0, v2.y, oa0[5]);
            oa0[6] = ffma2(pd0, v3.x, oa0[6]);
            oa0[7] = ffma2(pd0, v3.y, oa0[7]);
            oa1[0] = ffma2(pd1, v0.x, oa1[0]);
            oa1[1] = ffma2(pd1, v0.y, oa1[1]);
            oa1[2] = ffma2(pd1, v1.x, oa1[2]);
            oa1[3] = ffma2(pd1, v1.y, oa1[3]);
            oa1[4] = ffma2(pd1, v2.x, oa1[4]);
            oa1[5] = ffma2(pd1, v2.y, oa1[5]);
            oa1[6] = ffma2(pd1, v3.x, oa1[6]);
            oa1[7] = ffma2(pd1, v3.y, oa1[7]);
        }
    }

    float i0 = 1.f / l0, i1 = 1.f / l1;
    size_t ob0 = ((size_t)(b * SS + qt * 64 + r0)) * DD + h * HD + cg * 16;
    size_t ob1 = ob0 + DD;
    float o0[16], o1[16];
    #pragma unroll
    for (int c = 0; c < 8; c++) {
        float2 u0 = unpk(oa0[c]); o0[2*c] = u0.x * i0; o0[2*c+1] = u0.y * i0;
        float2 u1 = unpk(oa1[c]); o1[2*c] = u1.x * i1; o1[2*c+1] = u1.y * i1;
    }
    #pragma unroll
    for (int q = 0; q < 4; q++) {
        *(float4*)&g_o[ob0 + q*4] = make_float4(o0[q*4], o0[q*4+1], o0[q*4+2], o0[q*4+3]);
        *(float4*)&g_o[ob1 + q*4] = make_float4(o1[q*4], o1[q*4+1], o1[q*4+2], o1[q*4+3]);
    }
}

// ---------------------------------------------------------------------------
extern "C" void kernel_launch(void* const* d_in, const int* in_sizes, int n_in,
                              void* d_out, int out_size)
{
    const float* x          = (const float*)d_in[0];
    const float* rotary_cos = (const float*)d_in[1];
    const float* rotary_sin = (const float*)d_in[2];
    const float* c          = (const float*)d_in[3];
    const float* norm1_w    = (const float*)d_in[4];
    const float* qkv_w      = (const float*)d_in[5];
    const float* out_w      = (const float*)d_in[6];
    const float* norm2_w    = (const float*)d_in[7];
    const float* fc1_w      = (const float*)d_in[8];
    const float* fc1_b      = (const float*)d_in[9];
    const float* fc2_w      = (const float*)d_in[10];
    const float* fc2_b      = (const float*)d_in[11];
    const float* ada_w      = (const float*)d_in[12];
    const float* ada_b      = (const float*)d_in[13];
    float* out = (float*)d_out;

    float* p_h;    cudaGetSymbolAddress((void**)&p_h, g_h);
    float* p_qkv;  cudaGetSymbolAddress((void**)&p_qkv, g_qkv);
    float* p_o;    cudaGetSymbolAddress((void**)&p_o, g_o);
    float* p_xmid; cudaGetSymbolAddress((void**)&p_xmid, g_xmid);
    float* p_mlp;  cudaGetSymbolAddress((void**)&p_mlp, g_mlp);

    // 1) adaLN mods
    k_mods<<<(BB * D6 * 32 + 255) / 256, 256>>>(c, ada_w, ada_b);

    // 2) LN1 + modulate (scale_msa @1024, shift_msa @0) -> g_h
    k_ln_mod<<<MM, 256>>>(x, norm1_w, 1 * DD, 0 * DD, p_h);

    // 3) QKV GEMM -> g_qkv
    k_gemm<0><<<dim3(D3 / 128, MM / 128), 256>>>(p_h, qkv_w, nullptr, nullptr,
                                                 p_qkv, MM, D3, DD, 0);

    // 4) RoPE in place on q,k,v
    k_rope<<<(BB * SS * 3 * HH * 32) / 256, 256>>>(rotary_cos, rotary_sin);

    // 5) Attention -> g_o
    k_attn<<<dim3(SS / 64, HH, BB), 128>>>();

    // 6) out proj + gate_msa (@2048) + residual(x) -> g_xmid
    k_gemm<1><<<dim3(DD / 128, MM / 128), 256>>>(p_o, out_w, nullptr, x,
                                                 p_xmid, MM, DD, DD, 2 * DD);

    // 7) LN2 + modulate (scale_mlp @4096, shift_mlp @3072) -> g_h
    k_ln_mod<<<MM, 256>>>(p_xmid, norm2_w, 4 * DD, 3 * DD, p_h);

    // 8) fc1 + bias + exact GELU -> g_mlp
    k_gemm<2><<<dim3(D4 / 128, MM / 128), 256>>>(p_h, fc1_w, fc1_b, nullptr,
                                                 p_mlp, MM, D4, DD, 0);

    // 9) fc2 + bias, gate_mlp (@5120), + residual(g_xmid) -> d_out
    k_gemm<3><<<dim3(DD / 128, MM / 128), 256>>>(p_mlp, fc2_w, fc2_b, p_xmid,
                                                 out, MM, DD, D4, 5 * DD);
}

// round 5
// speedup vs baseline: 1.8161x; 1.5622x over previous
#include <cuda_runtime.h>
#include <cuda_bf16.h>
#include <math.h>

// Problem constants
#define BB 2
#define SS 2048
#define DD 1024
#define HH 16
#define HD 64
#define CC 1024
#define MM (BB*SS)          // 4096 rows
#define D3 (3*DD)           // 3072
#define D4 (4*DD)           // 4096
#define D6 (6*DD)           // 6144

typedef unsigned long long u64;
typedef unsigned int u32;

__device__ __forceinline__ u64 dup2(float v) {
    u64 r; asm("mov.b64 %0,{%1,%1};" : "=l"(r) : "f"(v)); return r;
}
__device__ __forceinline__ u64 ffma2(u64 a, u64 b, u64 c) {
    u64 d; asm("fma.rn.f32x2 %0,%1,%2,%3;" : "=l"(d) : "l"(a), "l"(b), "l"(c)); return d;
}
__device__ __forceinline__ u64 fmul2(u64 a, u64 b) {
    u64 d; asm("mul.rn.f32x2 %0,%1,%2;" : "=l"(d) : "l"(a), "l"(b)); return d;
}
__device__ __forceinline__ float2 unpk(u64 v) {
    float2 r; asm("mov.b64 {%0,%1},%2;" : "=f"(r.x), "=f"(r.y) : "l"(v)); return r;
}
__device__ __forceinline__ u32 to_tf32(float f) {
    u32 r; asm("cvt.rna.tf32.f32 %0,%1;" : "=r"(r) : "f"(f)); return r;
}

// Scratch (device globals; no allocation allowed)
__device__ float g_mods[BB*D6];
__device__ float g_h[MM*DD];       // LN1 out, later LN2 out
__device__ float g_qkv[MM*D3];
__device__ float g_o[MM*DD];
__device__ float g_xmid[MM*DD];
__device__ float g_mlp[MM*D4];

// ---------------------------------------------------------------------------
// 1) mods = c @ ada_w.T + ada_b
// ---------------------------------------------------------------------------
__global__ void k_mods(const float* __restrict__ c,
                       const float* __restrict__ ada_w,
                       const float* __restrict__ ada_b)
{
    int gw = (blockIdx.x * blockDim.x + threadIdx.x) >> 5;
    int lane = threadIdx.x & 31;
    if (gw >= BB * D6) return;
    int b = gw / D6, j = gw - b * D6;
    const float* cv = c + (size_t)b * CC;
    const float* wv = ada_w + (size_t)j * CC;
    float s = 0.f;
    #pragma unroll 4
    for (int k = lane; k < CC; k += 32) s += cv[k] * wv[k];
    #pragma unroll
    for (int o = 16; o > 0; o >>= 1) s += __shfl_xor_sync(0xffffffffu, s, o);
    if (lane == 0) g_mods[gw] = s + ada_b[j];
}

// ---------------------------------------------------------------------------
// 2) LayerNorm + adaLN modulate
// ---------------------------------------------------------------------------
__global__ void __launch_bounds__(256) k_ln_mod(const float* __restrict__ x,
                                                const float* __restrict__ w,
                                                int scale_off, int shift_off,
                                                float* __restrict__ out)
{
    int row = blockIdx.x;
    int b = row >> 11;
    const float4* xr = (const float4*)(x + (size_t)row * DD);
    int t = threadIdx.x;
    float4 xv = xr[t];
    float s  = xv.x + xv.y + xv.z + xv.w;
    float ss = xv.x*xv.x + xv.y*xv.y + xv.z*xv.z + xv.w*xv.w;
    #pragma unroll
    for (int o = 16; o > 0; o >>= 1) {
        s  += __shfl_xor_sync(0xffffffffu, s, o);
        ss += __shfl_xor_sync(0xffffffffu, ss, o);
    }
    __shared__ float sm[8], sm2[8];
    int wid = t >> 5, lane = t & 31;
    if (lane == 0) { sm[wid] = s; sm2[wid] = ss; }
    __syncthreads();
    if (t == 0) {
        float a = 0.f, a2 = 0.f;
        #pragma unroll
        for (int i = 0; i < 8; i++) { a += sm[i]; a2 += sm2[i]; }
        sm[0] = a; sm2[0] = a2;
    }
    __syncthreads();
    float mu  = sm[0]  * (1.f / DD);
    float var = sm2[0] * (1.f / DD) - mu * mu;
    float rstd = rsqrtf(var + 1e-5f);
    const float* md = g_mods + (size_t)b * D6;
    int j = t * 4;
    float4 wv = *(const float4*)(w + j);
    float4 sc = *(const float4*)(md + scale_off + j);
    float4 sh = *(const float4*)(md + shift_off + j);
    float4 ov;
    ov.x = (xv.x - mu) * rstd * wv.x * (1.f + sc.x) + sh.x;
    ov.y = (xv.y - mu) * rstd * wv.y * (1.f + sc.y) + sh.y;
    ov.z = (xv.z - mu) * rstd * wv.z * (1.f + sc.z) + sh.z;
    ov.w = (xv.w - mu) * rstd * wv.w * (1.f + sc.w) + sh.w;
    ((float4*)(out + (size_t)row * DD))[t] = ov;
}

// ---------------------------------------------------------------------------
// 3) tf32 tensor-core GEMM: C[M,N] = A[M,K] @ Bw[N,K]^T (+ epilogue)
//    128x128x32 tile, 256 threads (8 warps, 2x4), warp = 64x32 via
//    4x4 m16n8k8 mma tiles. SMEM stride 36 floats -> conflict-free frag LDS.
//    EPI: 0=store, 1=gate*acc+add, 2=gelu(acc+bias), 3=gate*(acc+bias)+add
// ---------------------------------------------------------------------------
#define SMS 36   // smem row stride (floats)

template<int EPI>
__global__ void __launch_bounds__(256) k_gemm(const float* __restrict__ A,
                                              const float* __restrict__ Bw,
                                              const float* __restrict__ bias,
                                              const float* __restrict__ add,
                                              float* __restrict__ C,
                                              int M, int N, int K, int gate_off)
{
    __shared__ u32 As[128 * SMS];
    __shared__ u32 Bs[128 * SMS];

    const int tid = threadIdx.x;
    const int wid = tid >> 5, lane = tid & 31;
    const int warp_m = wid & 1;        // 0..1  (64 rows each)
    const int warp_n = wid >> 1;       // 0..3  (32 cols each)
    const int gid = lane >> 2, tig = lane & 3;
    const int bm = blockIdx.y * 128, bn = blockIdx.x * 128;

    // GMEM load mapping: thread -> row (tid>>1), 16 consecutive k (tid&1)*16
    const int arow = tid >> 1;
    const int ak = (tid & 1) * 16;
    const float* Ap = A  + (size_t)(bm + arow) * K + ak;
    const float* Bp = Bw + (size_t)(bn + arow) * K + ak;

    float acc[4][4][4];
    #pragma unroll
    for (int mt = 0; mt < 4; mt++)
        #pragma unroll
        for (int nt = 0; nt < 4; nt++)
            #pragma unroll
            for (int r = 0; r < 4; r++) acc[mt][nt][r] = 0.f;

    // prefetch first tile
    float4 pa[4], pb[4];
    #pragma unroll
    for (int j = 0; j < 4; j++) {
        pa[j] = *(const float4*)(Ap + j * 4);
        pb[j] = *(const float4*)(Bp + j * 4);
    }

    for (int k0 = 0; k0 < K; k0 += 32) {
        __syncthreads();   // previous compute done before overwrite
        #pragma unroll
        for (int j = 0; j < 4; j++) {
            u32* as = &As[arow * SMS + ak + j * 4];
            as[0] = to_tf32(pa[j].x); as[1] = to_tf32(pa[j].y);
            as[2] = to_tf32(pa[j].z); as[3] = to_tf32(pa[j].w);
            u32* bs = &Bs[arow * SMS + ak + j * 4];
            bs[0] = to_tf32(pb[j].x); bs[1] = to_tf32(pb[j].y);
            bs[2] = to_tf32(pb[j].z); bs[3] = to_tf32(pb[j].w);
        }
        __syncthreads();

        // prefetch next tile while computing
        if (k0 + 32 < K) {
            #pragma unroll
            for (int j = 0; j < 4; j++) {
                pa[j] = *(const float4*)(Ap + k0 + 32 + j * 4);
                pb[j] = *(const float4*)(Bp + k0 + 32 + j * 4);
            }
        }

        #pragma unroll
        for (int ks = 0; ks < 4; ks++) {
            const int kb = ks * 8;
            u32 afr[4][4];
            #pragma unroll
            for (int mt = 0; mt < 4; mt++) {
                int m0 = warp_m * 64 + mt * 16;
                afr[mt][0] = As[(m0 + gid)     * SMS + kb + tig];
                afr[mt][1] = As[(m0 + gid + 8) * SMS + kb + tig];
                afr[mt][2] = As[(m0 + gid)     * SMS + kb + tig + 4];
                afr[mt][3] = As[(m0 + gid + 8) * SMS + kb + tig + 4];
            }
            u32 bfr[4][2];
            #pragma unroll
            for (int nt = 0; nt < 4; nt++) {
                int n0 = warp_n * 32 + nt * 8;
                bfr[nt][0] = Bs[(n0 + gid) * SMS + kb + tig];
                bfr[nt][1] = Bs[(n0 + gid) * SMS + kb + tig + 4];
            }
            #pragma unroll
            for (int mt = 0; mt < 4; mt++)
                #pragma unroll
                for (int nt = 0; nt < 4; nt++) {
                    asm volatile(
                        "mma.sync.aligned.m16n8k8.row.col.f32.tf32.tf32.f32 "
                        "{%0,%1,%2,%3},{%4,%5,%6,%7},{%8,%9},{%0,%1,%2,%3};"
                        : "+f"(acc[mt][nt][0]), "+f"(acc[mt][nt][1]),
                          "+f"(acc[mt][nt][2]), "+f"(acc[mt][nt][3])
                        : "r"(afr[mt][0]), "r"(afr[mt][1]),
                          "r"(afr[mt][2]), "r"(afr[mt][3]),
                          "r"(bfr[nt][0]), "r"(bfr[nt][1]));
                }
        }
    }

    // Epilogue. c0,c1 -> (row m, cols n,n+1); c2,c3 -> (row m+8)
    #pragma unroll
    for (int mt = 0; mt < 4; mt++) {
        #pragma unroll
        for (int half = 0; half < 2; half++) {
            int m = bm + warp_m * 64 + mt * 16 + gid + half * 8;
            int bb = m >> 11;
            #pragma unroll
            for (int nt = 0; nt < 4; nt++) {
                int n = bn + warp_n * 32 + nt * 8 + tig * 2;
                float v0 = acc[mt][nt][half * 2];
                float v1 = acc[mt][nt][half * 2 + 1];
                if (EPI == 0) {
                    // passthrough
                } else if (EPI == 1) {
                    v0 = g_mods[(size_t)bb * D6 + gate_off + n]     * v0
                         + add[(size_t)m * N + n];
                    v1 = g_mods[(size_t)bb * D6 + gate_off + n + 1] * v1
                         + add[(size_t)m * N + n + 1];
                } else if (EPI == 2) {
                    float t0 = v0 + bias[n],     t1 = v1 + bias[n + 1];
                    v0 = 0.5f * t0 * (1.f + erff(t0 * 0.70710678118654752f));
                    v1 = 0.5f * t1 * (1.f + erff(t1 * 0.70710678118654752f));
                } else {
                    float t0 = v0 + bias[n],     t1 = v1 + bias[n + 1];
                    v0 = g_mods[(size_t)bb * D6 + gate_off + n]     * t0
                         + add[(size_t)m * DD + n];
                    v1 = g_mods[(size_t)bb * D6 + gate_off + n + 1] * t1
                         + add[(size_t)m * DD + n + 1];
                }
                *(float2*)&C[(size_t)m * N + n] = make_float2(v0, v1);
            }
        }
    }
}

// ---------------------------------------------------------------------------
// 4) RoPE in place on all of q,k,v (reference applies it to v too)
// ---------------------------------------------------------------------------
__global__ void k_rope(const float* __restrict__ cosT, const float* __restrict__ sinT)
{
    int t = blockIdx.x * blockDim.x + threadIdx.x;
    if (t >= BB * SS * 3 * HH * 32) return;
    int d  = t & 31;  int u = t >> 5;
    int h  = u & 15;  u >>= 4;
    int m3 = u % 3;   u /= 3;
    int s  = u & 2047;
    int b  = u >> 11;
    size_t base = ((((size_t)(b * SS + s)) * 3 + m3) * HH + h) * HD;
    float c  = cosT[s * HD + d];
    float sn = sinT[s * HD + d];
    float v1 = g_qkv[base + d];
    float v2 = g_qkv[base + d + 32];
    g_qkv[base + d]      = v1 * c - v2 * sn;
    g_qkv[base + d + 32] = v2 * c + v1 * sn;
}

// ---------------------------------------------------------------------------
// 5) Flash attention fp32 with packed f32x2 math (unchanged, known-good).
// ---------------------------------------------------------------------------
__global__ void __launch_bounds__(128) k_attn()
{
    __shared__ float Qs[64][68];
    __shared__ float Kts[64][36];   // [d][token]
    __shared__ float Vs[32][68];
    __shared__ float Ps[64][33];

    int qt = blockIdx.x, h = blockIdx.y, b = blockIdx.z;
    int tid = threadIdx.x;
    int rg = tid >> 2, cg = tid & 3;
    int r0 = rg * 2, r1 = r0 + 1;

    size_t qbase = (((size_t)(b * SS + qt * 64)) * 3 + 0) * DD + h * HD;
    #pragma unroll
    for (int l = 0; l < 8; l++) {
        int id = tid + l * 128;
        int r = id >> 4, c4 = (id & 15) * 4;
        float4 v = *(const float4*)(g_qkv + qbase + (size_t)r * D3 + c4);
        *(float4*)&Qs[r][c4] = v;
    }

    float m0 = -1e30f, m1 = -1e30f, l0 = 0.f, l1 = 0.f;
    u64 oa0[8], oa1[8];
    #pragma unroll
    for (int c = 0; c < 8; c++) { oa0[c] = 0ull; oa1[c] = 0ull; }

    for (int kt = 0; kt < SS / 32; kt++) {
        __syncthreads();
        size_t kbase = (((size_t)(b * SS + kt * 32)) * 3 + 1) * DD + h * HD;
        size_t vbase = kbase + DD;
        #pragma unroll
        for (int l = 0; l < 4; l++) {
            int id = tid + l * 128;
            int r = id >> 4, c4 = (id & 15) * 4;
            float4 kv = *(const float4*)(g_qkv + kbase + (size_t)r * D3 + c4);
            Kts[c4+0][r] = kv.x; Kts[c4+1][r] = kv.y;
            Kts[c4+2][r] = kv.z; Kts[c4+3][r] = kv.w;
            float4 vv = *(const float4*)(g_qkv + vbase + (size_t)r * D3 + c4);
            *(float4*)&Vs[r][c4] = vv;
        }
        __syncthreads();

        u64 s20[4] = {0ull,0ull,0ull,0ull};
        u64 s21[4] = {0ull,0ull,0ull,0ull};
        #pragma unroll 4
        for (int d4 = 0; d4 < 64; d4 += 4) {
            float4 q0 = *(const float4*)&Qs[r0][d4];
            float4 q1 = *(const float4*)&Qs[r1][d4];
            float qa[4] = { q0.x, q0.y, q0.z, q0.w };
            float qb[4] = { q1.x, q1.y, q1.z, q1.w };
            #pragma unroll
            for (int dd = 0; dd < 4; dd++) {
                ulonglong2 k0v = *(const ulonglong2*)&Kts[d4+dd][cg * 8];
                ulonglong2 k1v = *(const ulonglong2*)&Kts[d4+dd][cg * 8 + 4];
                u64 qd0 = dup2(qa[dd]);
                u64 qd1 = dup2(qb[dd]);
                s20[0] = ffma2(qd0, k0v.x, s20[0]);
                s20[1] = ffma2(qd0, k0v.y, s20[1]);
                s20[2] = ffma2(qd0, k1v.x, s20[2]);
                s20[3] = ffma2(qd0, k1v.y, s20[3]);
                s21[0] = ffma2(qd1, k0v.x, s21[0]);
                s21[1] = ffma2(qd1, k0v.y, s21[1]);
                s21[2] = ffma2(qd1, k1v.x, s21[2]);
                s21[3] = ffma2(qd1, k1v.y, s21[3]);
            }
        }
        float s0[8], s1[8];
        #pragma unroll
        for (int j = 0; j < 4; j++) {
            float2 u0 = unpk(s20[j]); s0[2*j] = u0.x; s0[2*j+1] = u0.y;
            float2 u1 = unpk(s21[j]); s1[2*j] = u1.x; s1[2*j+1] = u1.y;
        }

        float mt0 = -1e30f, mt1 = -1e30f;
        #pragma unroll
        for (int c = 0; c < 8; c++) {
            s0[c] *= 0.125f; s1[c] *= 0.125f;
            mt0 = fmaxf(mt0, s0[c]); mt1 = fmaxf(mt1, s1[c]);
        }
        mt0 = fmaxf(mt0, __shfl_xor_sync(0xffffffffu, mt0, 1));
        mt0 = fmaxf(mt0, __shfl_xor_sync(0xffffffffu, mt0, 2));
        mt1 = fmaxf(mt1, __shfl_xor_sync(0xffffffffu, mt1, 1));
        mt1 = fmaxf(mt1, __shfl_xor_sync(0xffffffffu, mt1, 2));
        float mn0 = fmaxf(m0, mt0), mn1 = fmaxf(m1, mt1);
        float a0 = __expf(m0 - mn0), a1 = __expf(m1 - mn1);
        float lt0 = 0.f, lt1 = 0.f;
        #pragma unroll
        for (int c = 0; c < 8; c++) {
            float p0 = __expf(s0[c] - mn0);
            float p1 = __expf(s1[c] - mn1);
            Ps[r0][cg * 8 + c] = p0;
            Ps[r1][cg * 8 + c] = p1;
            lt0 += p0; lt1 += p1;
        }
        lt0 += __shfl_xor_sync(0xffffffffu, lt0, 1);
        lt0 += __shfl_xor_sync(0xffffffffu, lt0, 2);
        lt1 += __shfl_xor_sync(0xffffffffu, lt1, 1);
        lt1 += __shfl_xor_sync(0xffffffffu, lt1, 2);
        l0 = l0 * a0 + lt0;  m0 = mn0;
        l1 = l1 * a1 + lt1;  m1 = mn1;
        u64 a0d = dup2(a0), a1d = dup2(a1);
        #pragma unroll
        for (int c = 0; c < 8; c++) {
            oa0[c] = fmul2(oa0[c], a0d);
            oa1[c] = fmul2(oa1[c], a1d);
        }
        __syncwarp();

        #pragma unroll 4
        for (int col = 0; col < 32; col++) {
            float p0 = Ps[r0][col], p1 = Ps[r1][col];
            ulonglong2 v0 = *(const ulonglong2*)&Vs[col][cg * 16];
            ulonglong2 v1 = *(const ulonglong2*)&Vs[col][cg * 16 + 4];
            ulonglong2 v2 = *(const ulonglong2*)&Vs[col][cg * 16 + 8];
            ulonglong2 v3 = *(const ulonglong2*)&Vs[col][cg * 16 + 12];
            u64 pd0 = dup2(p0), pd1 = dup2(p1);
            oa0[0] = ffma2(pd0, v0.x, oa0[0]);
            oa0[1] = ffma2(pd0, v0.y, oa0[1]);
            oa0[2] = ffma2(pd0, v1.x, oa0[2]);
            oa0[3] = ffma2(pd0, v1.y, oa0[3]);
            oa0[4] = ffma2(pd0, v2.x, oa0[4]);
            oa0[5] = ffma2(pd0, v2.y, oa0[5]);
            oa0[6] = ffma2(pd0, v3.x, oa0[6]);
            oa0[7] = ffma2(pd0, v3.y, oa0[7]);
            oa1[0] = ffma2(pd1, v0.x, oa1[0]);
            oa1[1] = ffma2(pd1, v0.y, oa1[1]);
            oa1[2] = ffma2(pd1, v1.x, oa1[2]);
            oa1[3] = ffma2(pd1, v1.y, oa1[3]);
            oa1[4] = ffma2(pd1, v2.x, oa1[4]);
            oa1[5] = ffma2(pd1, v2.y, oa1[5]);
            oa1[6] = ffma2(pd1, v3.x, oa1[6]);
            oa1[7] = ffma2(pd1, v3.y, oa1[7]);
        }
    }

    float i0 = 1.f / l0, i1 = 1.f / l1;
    size_t ob0 = ((size_t)(b * SS + qt * 64 + r0)) * DD + h * HD + cg * 16;
    size_t ob1 = ob0 + DD;
    float o0[16], o1[16];
    #pragma unroll
    for (int c = 0; c < 8; c++) {
        float2 u0 = unpk(oa0[c]); o0[2*c] = u0.x * i0; o0[2*c+1] = u0.y * i0;
        float2 u1 = unpk(oa1[c]); o1[2*c] = u1.x * i1; o1[2*c+1] = u1.y * i1;
    }
    #pragma unroll
    for (int q = 0; q < 4; q++) {
        *(float4*)&g_o[ob0 + q*4] = make_float4(o0[q*4], o0[q*4+1], o0[q*4+2], o0[q*4+3]);
        *(float4*)&g_o[ob1 + q*4] = make_float4(o1[q*4], o1[q*4+1], o1[q*4+2], o1[q*4+3]);
    }
}

// ---------------------------------------------------------------------------
extern "C" void kernel_launch(void* const* d_in, const int* in_sizes, int n_in,
                              void* d_out, int out_size)
{
    const float* x          = (const float*)d_in[0];
    const float* rotary_cos = (const float*)d_in[1];
    const float* rotary_sin = (const float*)d_in[2];
    const float* c          = (const float*)d_in[3];
    const float* norm1_w    = (const float*)d_in[4];
    const float* qkv_w      = (const float*)d_in[5];
    const float* out_w      = (const float*)d_in[6];
    const float* norm2_w    = (const float*)d_in[7];
    const float* fc1_w      = (const float*)d_in[8];
    const float* fc1_b      = (const float*)d_in[9];
    const float* fc2_w      = (const float*)d_in[10];
    const float* fc2_b      = (const float*)d_in[11];
    const float* ada_w      = (const float*)d_in[12];
    const float* ada_b      = (const float*)d_in[13];
    float* out = (float*)d_out;

    float* p_h;    cudaGetSymbolAddress((void**)&p_h, g_h);
    float* p_qkv;  cudaGetSymbolAddress((void**)&p_qkv, g_qkv);
    float* p_o;    cudaGetSymbolAddress((void**)&p_o, g_o);
    float* p_xmid; cudaGetSymbolAddress((void**)&p_xmid, g_xmid);
    float* p_mlp;  cudaGetSymbolAddress((void**)&p_mlp, g_mlp);

    // 1) adaLN mods
    k_mods<<<(BB * D6 * 32 + 255) / 256, 256>>>(c, ada_w, ada_b);

    // 2) LN1 + modulate (scale_msa @1024, shift_msa @0) -> g_h
    k_ln_mod<<<MM, 256>>>(x, norm1_w, 1 * DD, 0 * DD, p_h);

    // 3) QKV GEMM -> g_qkv
    k_gemm<0><<<dim3(D3 / 128, MM / 128), 256>>>(p_h, qkv_w, nullptr, nullptr,
                                                 p_qkv, MM, D3, DD, 0);

    // 4) RoPE in place on q,k,v
    k_rope<<<(BB * SS * 3 * HH * 32) / 256, 256>>>(rotary_cos, rotary_sin);

    // 5) Attention -> g_o
    k_attn<<<dim3(SS / 64, HH, BB), 128>>>();

    // 6) out proj + gate_msa (@2048) + residual(x) -> g_xmid
    k_gemm<1><<<dim3(DD / 128, MM / 128), 256>>>(p_o, out_w, nullptr, x,
                                                 p_xmid, MM, DD, DD, 2 * DD);

    // 7) LN2 + modulate (scale_mlp @4096, shift_mlp @3072) -> g_h
    k_ln_mod<<<MM, 256>>>(p_xmid, norm2_w, 4 * DD, 3 * DD, p_h);

    // 8) fc1 + bias + exact GELU -> g_mlp
    k_gemm<2><<<dim3(D4 / 128, MM / 128), 256>>>(p_h, fc1_w, fc1_b, nullptr,
                                                 p_mlp, MM, D4, DD, 0);

    // 9) fc2 + bias, gate_mlp (@5120), + residual(g_xmid) -> d_out
    k_gemm<3><<<dim3(DD / 128, MM / 128), 256>>>(p_mlp, fc2_w, fc2_b, p_xmid,
                                                 out, MM, DD, D4, 5 * DD);
}

// round 6
// speedup vs baseline: 2.9938x; 1.6484x over previous
#include <cuda_runtime.h>
#include <cuda_bf16.h>
#include <math.h>

// Problem constants
#define BB 2
#define SS 2048
#define DD 1024
#define HH 16
#define HD 64
#define CC 1024
#define MM (BB*SS)          // 4096 rows
#define D3 (3*DD)           // 3072
#define D4 (4*DD)           // 4096
#define D6 (6*DD)           // 6144

typedef unsigned long long u64;
typedef unsigned int u32;

__device__ __forceinline__ u32 to_tf32(float f) {
    u32 r; asm("cvt.rna.tf32.f32 %0,%1;" : "=r"(r) : "f"(f)); return r;
}

// Scratch (device globals; no allocation allowed)
__device__ float g_mods[BB*D6];
__device__ float g_h[MM*DD];       // LN1 out, later LN2 out
__device__ float g_qkv[MM*D3];
__device__ float g_o[MM*DD];
__device__ float g_xmid[MM*DD];
__device__ float g_mlp[MM*D4];

// ---------------------------------------------------------------------------
// 1) mods = c @ ada_w.T + ada_b
// ---------------------------------------------------------------------------
__global__ void k_mods(const float* __restrict__ c,
                       const float* __restrict__ ada_w,
                       const float* __restrict__ ada_b)
{
    int gw = (blockIdx.x * blockDim.x + threadIdx.x) >> 5;
    int lane = threadIdx.x & 31;
    if (gw >= BB * D6) return;
    int b = gw / D6, j = gw - b * D6;
    const float* cv = c + (size_t)b * CC;
    const float* wv = ada_w + (size_t)j * CC;
    float s = 0.f;
    #pragma unroll 4
    for (int k = lane; k < CC; k += 32) s += cv[k] * wv[k];
    #pragma unroll
    for (int o = 16; o > 0; o >>= 1) s += __shfl_xor_sync(0xffffffffu, s, o);
    if (lane == 0) g_mods[gw] = s + ada_b[j];
}

// ---------------------------------------------------------------------------
// 2) LayerNorm + adaLN modulate
// ---------------------------------------------------------------------------
__global__ void __launch_bounds__(256) k_ln_mod(const float* __restrict__ x,
                                                const float* __restrict__ w,
                                                int scale_off, int shift_off,
                                                float* __restrict__ out)
{
    int row = blockIdx.x;
    int b = row >> 11;
    const float4* xr = (const float4*)(x + (size_t)row * DD);
    int t = threadIdx.x;
    float4 xv = xr[t];
    float s  = xv.x + xv.y + xv.z + xv.w;
    float ss = xv.x*xv.x + xv.y*xv.y + xv.z*xv.z + xv.w*xv.w;
    #pragma unroll
    for (int o = 16; o > 0; o >>= 1) {
        s  += __shfl_xor_sync(0xffffffffu, s, o);
        ss += __shfl_xor_sync(0xffffffffu, ss, o);
    }
    __shared__ float sm[8], sm2[8];
    int wid = t >> 5, lane = t & 31;
    if (lane == 0) { sm[wid] = s; sm2[wid] = ss; }
    __syncthreads();
    if (t == 0) {
        float a = 0.f, a2 = 0.f;
        #pragma unroll
        for (int i = 0; i < 8; i++) { a += sm[i]; a2 += sm2[i]; }
        sm[0] = a; sm2[0] = a2;
    }
    __syncthreads();
    float mu  = sm[0]  * (1.f / DD);
    float var = sm2[0] * (1.f / DD) - mu * mu;
    float rstd = rsqrtf(var + 1e-5f);
    const float* md = g_mods + (size_t)b * D6;
    int j = t * 4;
    float4 wv = *(const float4*)(w + j);
    float4 sc = *(const float4*)(md + scale_off + j);
    float4 sh = *(const float4*)(md + shift_off + j);
    float4 ov;
    ov.x = (xv.x - mu) * rstd * wv.x * (1.f + sc.x) + sh.x;
    ov.y = (xv.y - mu) * rstd * wv.y * (1.f + sc.y) + sh.y;
    ov.z = (xv.z - mu) * rstd * wv.z * (1.f + sc.z) + sh.z;
    ov.w = (xv.w - mu) * rstd * wv.w * (1.f + sc.w) + sh.w;
    ((float4*)(out + (size_t)row * DD))[t] = ov;
}

// ---------------------------------------------------------------------------
// 3) tf32 tensor-core GEMM: C[M,N] = A[M,K] @ Bw[N,K]^T (+ epilogue)
//    128x128x32 tile, 256 threads (8 warps, 2x4), warp = 64x32 via
//    4x4 m16n8k8 mma tiles. SMEM stride 36 floats -> conflict-free frag LDS.
//    EPI: 0=store, 1=gate*acc+add, 2=gelu(acc+bias), 3=gate*(acc+bias)+add
// ---------------------------------------------------------------------------
#define SMS 36   // smem row stride (floats)

template<int EPI>
__global__ void __launch_bounds__(256) k_gemm(const float* __restrict__ A,
                                              const float* __restrict__ Bw,
                                              const float* __restrict__ bias,
                                              const float* __restrict__ add,
                                              float* __restrict__ C,
                                              int M, int N, int K, int gate_off)
{
    __shared__ u32 As[128 * SMS];
    __shared__ u32 Bs[128 * SMS];

    const int tid = threadIdx.x;
    const int wid = tid >> 5, lane = tid & 31;
    const int warp_m = wid & 1;
    const int warp_n = wid >> 1;
    const int gid = lane >> 2, tig = lane & 3;
    const int bm = blockIdx.y * 128, bn = blockIdx.x * 128;

    const int arow = tid >> 1;
    const int ak = (tid & 1) * 16;
    const float* Ap = A  + (size_t)(bm + arow) * K + ak;
    const float* Bp = Bw + (size_t)(bn + arow) * K + ak;

    float acc[4][4][4];
    #pragma unroll
    for (int mt = 0; mt < 4; mt++)
        #pragma unroll
        for (int nt = 0; nt < 4; nt++)
            #pragma unroll
            for (int r = 0; r < 4; r++) acc[mt][nt][r] = 0.f;

    float4 pa[4], pb[4];
    #pragma unroll
    for (int j = 0; j < 4; j++) {
        pa[j] = *(const float4*)(Ap + j * 4);
        pb[j] = *(const float4*)(Bp + j * 4);
    }

    for (int k0 = 0; k0 < K; k0 += 32) {
        __syncthreads();
        #pragma unroll
        for (int j = 0; j < 4; j++) {
            u32* as = &As[arow * SMS + ak + j * 4];
            as[0] = to_tf32(pa[j].x); as[1] = to_tf32(pa[j].y);
            as[2] = to_tf32(pa[j].z); as[3] = to_tf32(pa[j].w);
            u32* bs = &Bs[arow * SMS + ak + j * 4];
            bs[0] = to_tf32(pb[j].x); bs[1] = to_tf32(pb[j].y);
            bs[2] = to_tf32(pb[j].z); bs[3] = to_tf32(pb[j].w);
        }
        __syncthreads();

        if (k0 + 32 < K) {
            #pragma unroll
            for (int j = 0; j < 4; j++) {
                pa[j] = *(const float4*)(Ap + k0 + 32 + j * 4);
                pb[j] = *(const float4*)(Bp + k0 + 32 + j * 4);
            }
        }

        #pragma unroll
        for (int ks = 0; ks < 4; ks++) {
            const int kb = ks * 8;
            u32 afr[4][4];
            #pragma unroll
            for (int mt = 0; mt < 4; mt++) {
                int m0 = warp_m * 64 + mt * 16;
                afr[mt][0] = As[(m0 + gid)     * SMS + kb + tig];
                afr[mt][1] = As[(m0 + gid + 8) * SMS + kb + tig];
                afr[mt][2] = As[(m0 + gid)     * SMS + kb + tig + 4];
                afr[mt][3] = As[(m0 + gid + 8) * SMS + kb + tig + 4];
            }
            u32 bfr[4][2];
            #pragma unroll
            for (int nt = 0; nt < 4; nt++) {
                int n0 = warp_n * 32 + nt * 8;
                bfr[nt][0] = Bs[(n0 + gid) * SMS + kb + tig];
                bfr[nt][1] = Bs[(n0 + gid) * SMS + kb + tig + 4];
            }
            #pragma unroll
            for (int mt = 0; mt < 4; mt++)
                #pragma unroll
                for (int nt = 0; nt < 4; nt++) {
                    asm volatile(
                        "mma.sync.aligned.m16n8k8.row.col.f32.tf32.tf32.f32 "
                        "{%0,%1,%2,%3},{%4,%5,%6,%7},{%8,%9},{%0,%1,%2,%3};"
                        : "+f"(acc[mt][nt][0]), "+f"(acc[mt][nt][1]),
                          "+f"(acc[mt][nt][2]), "+f"(acc[mt][nt][3])
                        : "r"(afr[mt][0]), "r"(afr[mt][1]),
                          "r"(afr[mt][2]), "r"(afr[mt][3]),
                          "r"(bfr[nt][0]), "r"(bfr[nt][1]));
                }
        }
    }

    #pragma unroll
    for (int mt = 0; mt < 4; mt++) {
        #pragma unroll
        for (int half = 0; half < 2; half++) {
            int m = bm + warp_m * 64 + mt * 16 + gid + half * 8;
            int bb = m >> 11;
            #pragma unroll
            for (int nt = 0; nt < 4; nt++) {
                int n = bn + warp_n * 32 + nt * 8 + tig * 2;
                float v0 = acc[mt][nt][half * 2];
                float v1 = acc[mt][nt][half * 2 + 1];
                if (EPI == 0) {
                } else if (EPI == 1) {
                    v0 = g_mods[(size_t)bb * D6 + gate_off + n]     * v0
                         + add[(size_t)m * N + n];
                    v1 = g_mods[(size_t)bb * D6 + gate_off + n + 1] * v1
                         + add[(size_t)m * N + n + 1];
                } else if (EPI == 2) {
                    float t0 = v0 + bias[n],     t1 = v1 + bias[n + 1];
                    v0 = 0.5f * t0 * (1.f + erff(t0 * 0.70710678118654752f));
                    v1 = 0.5f * t1 * (1.f + erff(t1 * 0.70710678118654752f));
                } else {
                    float t0 = v0 + bias[n],     t1 = v1 + bias[n + 1];
                    v0 = g_mods[(size_t)bb * D6 + gate_off + n]     * t0
                         + add[(size_t)m * DD + n];
                    v1 = g_mods[(size_t)bb * D6 + gate_off + n + 1] * t1
                         + add[(size_t)m * DD + n + 1];
                }
                *(float2*)&C[(size_t)m * N + n] = make_float2(v0, v1);
            }
        }
    }
}

// ---------------------------------------------------------------------------
// 4) RoPE in place on all of q,k,v (reference applies it to v too)
// ---------------------------------------------------------------------------
__global__ void k_rope(const float* __restrict__ cosT, const float* __restrict__ sinT)
{
    int t = blockIdx.x * blockDim.x + threadIdx.x;
    if (t >= BB * SS * 3 * HH * 32) return;
    int d  = t & 31;  int u = t >> 5;
    int h  = u & 15;  u >>= 4;
    int m3 = u % 3;   u /= 3;
    int s  = u & 2047;
    int b  = u >> 11;
    size_t base = ((((size_t)(b * SS + s)) * 3 + m3) * HH + h) * HD;
    float c  = cosT[s * HD + d];
    float sn = sinT[s * HD + d];
    float v1 = g_qkv[base + d];
    float v2 = g_qkv[base + d + 32];
    g_qkv[base + d]      = v1 * c - v2 * sn;
    g_qkv[base + d + 32] = v2 * c + v1 * sn;
}

// ---------------------------------------------------------------------------
// 5) Flash attention on tf32 tensor cores. Br=64, Bc=64, 4 warps.
//    Warp w owns query rows [w*16, w*16+16). Q fragments live in registers.
//    SMEM (dynamic): Ks[64][68], Vs[64][72], Ps[64][68] (Ps also stages Q).
//    Strides chosen so all fragment LDS are bank-conflict-free:
//      A-frag/B-frag row-indexed loads: stride 68 (= 4 mod 32)
//      V B-frag k-indexed loads:        stride 72 (= 8 mod 32)
// ---------------------------------------------------------------------------
#define KST 68
#define VST 72
#define ATT_SMEM ((64*KST + 64*VST + 64*KST) * 4)

__global__ void __launch_bounds__(128) k_attn()
{
    extern __shared__ u32 dyn[];
    u32* Ks = dyn;                       // [64][KST]
    u32* Vs = dyn + 64 * KST;            // [64][VST]
    u32* Ps = dyn + 64 * KST + 64 * VST; // [64][KST]

    int qt = blockIdx.x, h = blockIdx.y, b = blockIdx.z;
    int tid = threadIdx.x;
    int wid = tid >> 5, lane = tid & 31;
    int gid = lane >> 2, tig = lane & 3;
    int m0w = wid * 16;

    // Stage Q tile (64x64) into Ps as tf32
    size_t qbase = (((size_t)(b * SS + qt * 64)) * 3 + 0) * DD + h * HD;
    {
        int r = tid >> 1, c0 = (tid & 1) * 32;
        const float* src = g_qkv + qbase + (size_t)r * D3 + c0;
        u32* dst = Ps + r * KST + c0;
        #pragma unroll
        for (int j = 0; j < 8; j++) {
            float4 v = *(const float4*)(src + j * 4);
            dst[j*4+0] = to_tf32(v.x); dst[j*4+1] = to_tf32(v.y);
            dst[j*4+2] = to_tf32(v.z); dst[j*4+3] = to_tf32(v.w);
        }
    }
    __syncthreads();

    // Q A-fragments into registers (rows m0w..m0w+15, k = 0..63)
    u32 qa[8][4];
    #pragma unroll
    for (int ks = 0; ks < 8; ks++) {
        int kb = ks * 8;
        qa[ks][0] = Ps[(m0w + gid)     * KST + kb + tig];
        qa[ks][1] = Ps[(m0w + gid + 8) * KST + kb + tig];
        qa[ks][2] = Ps[(m0w + gid)     * KST + kb + tig + 4];
        qa[ks][3] = Ps[(m0w + gid + 8) * KST + kb + tig + 4];
    }
    // NOTE: Ps is reused for P below; the __syncthreads() at the top of the
    // first kt iteration orders these reads before any P writes.

    float mx0 = -1e30f, mx1 = -1e30f, l0 = 0.f, l1 = 0.f;
    float oa[8][4];
    #pragma unroll
    for (int nt = 0; nt < 8; nt++)
        #pragma unroll
        for (int r = 0; r < 4; r++) oa[nt][r] = 0.f;

    for (int kt = 0; kt < SS / 64; kt++) {
        __syncthreads();   // previous iteration's Ks/Vs/Ps readers done
        {
            int r = tid >> 1, c0 = (tid & 1) * 32;
            size_t kb_ = (((size_t)(b * SS + kt * 64 + r)) * 3 + 1) * DD + h * HD + c0;
            const float* ksrc = g_qkv + kb_;
            const float* vsrc = g_qkv + kb_ + DD;
            u32* kd = Ks + r * KST + c0;
            u32* vd = Vs + r * VST + c0;
            #pragma unroll
            for (int j = 0; j < 8; j++) {
                float4 v = *(const float4*)(ksrc + j * 4);
                kd[j*4+0] = to_tf32(v.x); kd[j*4+1] = to_tf32(v.y);
                kd[j*4+2] = to_tf32(v.z); kd[j*4+3] = to_tf32(v.w);
                float4 w = *(const float4*)(vsrc + j * 4);
                vd[j*4+0] = to_tf32(w.x); vd[j*4+1] = to_tf32(w.y);
                vd[j*4+2] = to_tf32(w.z); vd[j*4+3] = to_tf32(w.w);
            }
        }
        __syncthreads();

        // ---- S = Q @ K^T  (warp: 16 x 64) ----
        float sacc[8][4];
        #pragma unroll
        for (int nt = 0; nt < 8; nt++)
            #pragma unroll
            for (int r = 0; r < 4; r++) sacc[nt][r] = 0.f;

        #pragma unroll
        for (int ks = 0; ks < 8; ks++) {
            int kb = ks * 8;
            #pragma unroll
            for (int nt = 0; nt < 8; nt++) {
                u32 b0 = Ks[(nt * 8 + gid) * KST + kb + tig];
                u32 b1 = Ks[(nt * 8 + gid) * KST + kb + tig + 4];
                asm volatile(
                    "mma.sync.aligned.m16n8k8.row.col.f32.tf32.tf32.f32 "
                    "{%0,%1,%2,%3},{%4,%5,%6,%7},{%8,%9},{%0,%1,%2,%3};"
                    : "+f"(sacc[nt][0]), "+f"(sacc[nt][1]),
                      "+f"(sacc[nt][2]), "+f"(sacc[nt][3])
                    : "r"(qa[ks][0]), "r"(qa[ks][1]),
                      "r"(qa[ks][2]), "r"(qa[ks][3]),
                      "r"(b0), "r"(b1));
            }
        }

        // ---- online softmax (rows gid and gid+8; reduce over tig lanes) ----
        float mt0 = -1e30f, mt1 = -1e30f;
        #pragma unroll
        for (int nt = 0; nt < 8; nt++) {
            sacc[nt][0] *= 0.125f; sacc[nt][1] *= 0.125f;
            sacc[nt][2] *= 0.125f; sacc[nt][3] *= 0.125f;
            mt0 = fmaxf(mt0, fmaxf(sacc[nt][0], sacc[nt][1]));
            mt1 = fmaxf(mt1, fmaxf(sacc[nt][2], sacc[nt][3]));
        }
        mt0 = fmaxf(mt0, __shfl_xor_sync(0xffffffffu, mt0, 1));
        mt0 = fmaxf(mt0, __shfl_xor_sync(0xffffffffu, mt0, 2));
        mt1 = fmaxf(mt1, __shfl_xor_sync(0xffffffffu, mt1, 1));
        mt1 = fmaxf(mt1, __shfl_xor_sync(0xffffffffu, mt1, 2));
        float mn0 = fmaxf(mx0, mt0), mn1 = fmaxf(mx1, mt1);
        float a0 = __expf(mx0 - mn0), a1 = __expf(mx1 - mn1);
        float lt0 = 0.f, lt1 = 0.f;
        #pragma unroll
        for (int nt = 0; nt < 8; nt++) {
            float p0 = __expf(sacc[nt][0] - mn0);
            float p1 = __expf(sacc[nt][1] - mn0);
            float p2 = __expf(sacc[nt][2] - mn1);
            float p3 = __expf(sacc[nt][3] - mn1);
            lt0 += p0 + p1;  lt1 += p2 + p3;
            *(uint2*)&Ps[(m0w + gid)     * KST + nt * 8 + 2 * tig] =
                make_uint2(to_tf32(p0), to_tf32(p1));
            *(uint2*)&Ps[(m0w + gid + 8) * KST + nt * 8 + 2 * tig] =
                make_uint2(to_tf32(p2), to_tf32(p3));
        }
        lt0 += __shfl_xor_sync(0xffffffffu, lt0, 1);
        lt0 += __shfl_xor_sync(0xffffffffu, lt0, 2);
        lt1 += __shfl_xor_sync(0xffffffffu, lt1, 1);
        lt1 += __shfl_xor_sync(0xffffffffu, lt1, 2);
        l0 = l0 * a0 + lt0;  mx0 = mn0;
        l1 = l1 * a1 + lt1;  mx1 = mn1;
        #pragma unroll
        for (int nt = 0; nt < 8; nt++) {
            oa[nt][0] *= a0; oa[nt][1] *= a0;
            oa[nt][2] *= a1; oa[nt][3] *= a1;
        }
        __syncwarp();   // P rows of this warp written by this warp's lanes

        // ---- O += P @ V  (warp: 16 x 64, k = 64 tokens) ----
        #pragma unroll
        for (int ks = 0; ks < 8; ks++) {
            int kb = ks * 8;
            u32 pa0 = Ps[(m0w + gid)     * KST + kb + tig];
            u32 pa1 = Ps[(m0w + gid + 8) * KST + kb + tig];
            u32 pa2 = Ps[(m0w + gid)     * KST + kb + tig + 4];
            u32 pa3 = Ps[(m0w + gid + 8) * KST + kb + tig + 4];
            #pragma unroll
            for (int nt = 0; nt < 8; nt++) {
                u32 b0 = Vs[(kb + tig)     * VST + nt * 8 + gid];
                u32 b1 = Vs[(kb + tig + 4) * VST + nt * 8 + gid];
                asm volatile(
                    "mma.sync.aligned.m16n8k8.row.col.f32.tf32.tf32.f32 "
                    "{%0,%1,%2,%3},{%4,%5,%6,%7},{%8,%9},{%0,%1,%2,%3};"
                    : "+f"(oa[nt][0]), "+f"(oa[nt][1]),
                      "+f"(oa[nt][2]), "+f"(oa[nt][3])
                    : "r"(pa0), "r"(pa1), "r"(pa2), "r"(pa3),
                      "r"(b0), "r"(b1));
            }
        }
    }

    // ---- epilogue ----
    float i0 = 1.f / l0, i1 = 1.f / l1;
    int row0 = qt * 64 + m0w + gid;
    size_t ob0 = ((size_t)(b * SS + row0)) * DD + h * HD;
    size_t ob1 = ob0 + (size_t)8 * DD;
    #pragma unroll
    for (int nt = 0; nt < 8; nt++) {
        int cc = nt * 8 + 2 * tig;
        *(float2*)&g_o[ob0 + cc] = make_float2(oa[nt][0] * i0, oa[nt][1] * i0);
        *(float2*)&g_o[ob1 + cc] = make_float2(oa[nt][2] * i1, oa[nt][3] * i1);
    }
}

// ---------------------------------------------------------------------------
extern "C" void kernel_launch(void* const* d_in, const int* in_sizes, int n_in,
                              void* d_out, int out_size)
{
    const float* x          = (const float*)d_in[0];
    const float* rotary_cos = (const float*)d_in[1];
    const float* rotary_sin = (const float*)d_in[2];
    const float* c          = (const float*)d_in[3];
    const float* norm1_w    = (const float*)d_in[4];
    const float* qkv_w      = (const float*)d_in[5];
    const float* out_w      = (const float*)d_in[6];
    const float* norm2_w    = (const float*)d_in[7];
    const float* fc1_w      = (const float*)d_in[8];
    const float* fc1_b      = (const float*)d_in[9];
    const float* fc2_w      = (const float*)d_in[10];
    const float* fc2_b      = (const float*)d_in[11];
    const float* ada_w      = (const float*)d_in[12];
    const float* ada_b      = (const float*)d_in[13];
    float* out = (float*)d_out;

    float* p_h;    cudaGetSymbolAddress((void**)&p_h, g_h);
    float* p_qkv;  cudaGetSymbolAddress((void**)&p_qkv, g_qkv);
    float* p_o;    cudaGetSymbolAddress((void**)&p_o, g_o);
    float* p_xmid; cudaGetSymbolAddress((void**)&p_xmid, g_xmid);
    float* p_mlp;  cudaGetSymbolAddress((void**)&p_mlp, g_mlp);

    static int smem_set = 0;
    if (!smem_set) {
        cudaFuncSetAttribute(k_attn,
            cudaFuncAttributeMaxDynamicSharedMemorySize, ATT_SMEM);
        smem_set = 1;
    }

    // 1) adaLN mods
    k_mods<<<(BB * D6 * 32 + 255) / 256, 256>>>(c, ada_w, ada_b);

    // 2) LN1 + modulate (scale_msa @1024, shift_msa @0) -> g_h
    k_ln_mod<<<MM, 256>>>(x, norm1_w, 1 * DD, 0 * DD, p_h);

    // 3) QKV GEMM -> g_qkv
    k_gemm<0><<<dim3(D3 / 128, MM / 128), 256>>>(p_h, qkv_w, nullptr, nullptr,
                                                 p_qkv, MM, D3, DD, 0);

    // 4) RoPE in place on q,k,v
    k_rope<<<(BB * SS * 3 * HH * 32) / 256, 256>>>(rotary_cos, rotary_sin);

    // 5) Attention -> g_o
    k_attn<<<dim3(SS / 64, HH, BB), 128, ATT_SMEM>>>();

    // 6) out proj + gate_msa (@2048) + residual(x) -> g_xmid
    k_gemm<1><<<dim3(DD / 128, MM / 128), 256>>>(p_o, out_w, nullptr, x,
                                                 p_xmid, MM, DD, DD, 2 * DD);

    // 7) LN2 + modulate (scale_mlp @4096, shift_mlp @3072) -> g_h
    k_ln_mod<<<MM, 256>>>(p_xmid, norm2_w, 4 * DD, 3 * DD, p_h);

    // 8) fc1 + bias + exact GELU -> g_mlp
    k_gemm<2><<<dim3(D4 / 128, MM / 128), 256>>>(p_h, fc1_w, fc1_b, nullptr,
                                                 p_mlp, MM, D4, DD, 0);

    // 9) fc2 + bias, gate_mlp (@5120), + residual(g_xmid) -> d_out
    k_gemm<3><<<dim3(DD / 128, MM / 128), 256>>>(p_mlp, fc2_w, fc2_b, p_xmid,
                                                 out, MM, DD, D4, 5 * DD);
}